// round 5
// baseline (speedup 1.0000x reference)
#include <cuda_runtime.h>
#include <math_constants.h>

#define VOCAB   50257
#define NBEAM   8
#define TOPK    8
#define HIST    128
#define PARTS   16
#define CHUNK   3142            /* ceil(50257/16) */
#define TPB_A   256
#define REST4   262144          /* KV2*HEADS*SEQ*HDIM/4 */
#define KV_TOTAL 268435456LL    /* L*BEAM*KV2*HEADS*SEQ*HDIM */

__device__ float g_pm[NBEAM * PARTS];          // partial streaming-lse max
__device__ float g_ps[NBEAM * PARTS];          // partial sum exp(x - m)
__device__ float g_pv[NBEAM * PARTS * TOPK];   // per-part top-8 values
__device__ int   g_pi[NBEAM * PARTS * TOPK];   // per-part top-8 global indices
__device__ int   g_bi[NBEAM];

// ---------------------------------------------------------------------------
// Kernel 1: per (part, row) block. Single-pass register top-8 + streaming lse.
// ---------------------------------------------------------------------------
__global__ void __launch_bounds__(TPB_A) k_rowtop_part(const float* __restrict__ logits) {
    const int part = blockIdx.x, b = blockIdx.y;
    const int tid = threadIdx.x, lane = tid & 31, wid = tid >> 5;
    const int base = part * CHUNK;
    const float* __restrict__ row = logits + (long long)b * VOCAB;

    // per-thread sorted-desc top-8 (stable: ties keep earlier/lower index first)
    float v[TOPK]; int x[TOPK];
    #pragma unroll
    for (int j = 0; j < TOPK; j++) { v[j] = -CUDART_INF_F; x[j] = 0x7fffffff; }

    float m = -CUDART_INF_F, s = 0.f;
    for (int i = tid; i < CHUNK; i += TPB_A) {
        const int g = base + i;
        if (g < VOCAB) {
            const float val = __ldg(row + g);
            // streaming logsumexp
            if (val > m) { s = s * __expf(m - val) + 1.f; m = val; }
            else         { s += __expf(val - m); }
            // top-8 insert (ascending index scan + strict > keeps lowest idx on ties)
            if (val > v[TOPK - 1]) {
                v[TOPK - 1] = val; x[TOPK - 1] = g;
                #pragma unroll
                for (int j = TOPK - 1; j > 0; j--) {
                    if (v[j] > v[j - 1]) {
                        float tv = v[j]; v[j] = v[j - 1]; v[j - 1] = tv;
                        int   ti = x[j]; x[j] = x[j - 1]; x[j - 1] = ti;
                    }
                }
            }
        }
    }

    // --- warp lse merge ---
    {
        float mm = m, ss = s;
        #pragma unroll
        for (int off = 16; off; off >>= 1) {
            float om = __shfl_down_sync(0xffffffffu, mm, off);
            float os = __shfl_down_sync(0xffffffffu, ss, off);
            if (om > mm)                  { ss = ss * __expf(mm - om) + os; mm = om; }
            else if (om > -CUDART_INF_F)  { ss += os * __expf(om - mm); }
        }
        __shared__ float swm[8], sws[8];
        if (lane == 0) { swm[wid] = mm; sws[wid] = ss; }
        __syncthreads();
        if (wid == 0) {
            mm = (lane < 8) ? swm[lane] : -CUDART_INF_F;
            ss = (lane < 8) ? sws[lane] : 0.f;
            #pragma unroll
            for (int off = 4; off; off >>= 1) {
                float om = __shfl_down_sync(0xffffffffu, mm, off);
                float os = __shfl_down_sync(0xffffffffu, ss, off);
                if (om > mm)                  { ss = ss * __expf(mm - om) + os; mm = om; }
                else if (om > -CUDART_INF_F)  { ss += os * __expf(om - mm); }
            }
            if (lane == 0) { g_pm[b * PARTS + part] = mm; g_ps[b * PARTS + part] = ss; }
        }
    }

    // --- warp top-8 merge: 8 rounds of head-argmax, winner pops (all regs) ---
    float rv[TOPK]; int ri[TOPK];
    #pragma unroll
    for (int k = 0; k < TOPK; k++) {
        float bv = v[0]; int bidx = x[0];
        #pragma unroll
        for (int off = 16; off; off >>= 1) {
            float ov = __shfl_down_sync(0xffffffffu, bv, off);
            int   oi = __shfl_down_sync(0xffffffffu, bidx, off);
            if (ov > bv || (ov == bv && oi < bidx)) { bv = ov; bidx = oi; }
        }
        bv   = __shfl_sync(0xffffffffu, bv, 0);
        bidx = __shfl_sync(0xffffffffu, bidx, 0);
        if (x[0] == bidx && v[0] == bv) {   // this lane's head won -> pop
            #pragma unroll
            for (int j = 0; j < TOPK - 1; j++) { v[j] = v[j + 1]; x[j] = x[j + 1]; }
            v[TOPK - 1] = -CUDART_INF_F; x[TOPK - 1] = 0x7fffffff;
        }
        rv[k] = bv; ri[k] = bidx;
    }

    // --- block merge: 8 warp lists -> smem -> warp 0 pop-merge ---
    __shared__ float sw_v[8 * TOPK];
    __shared__ int   sw_i[8 * TOPK];
    if (lane == 0) {
        #pragma unroll
        for (int k = 0; k < TOPK; k++) { sw_v[wid * TOPK + k] = rv[k]; sw_i[wid * TOPK + k] = ri[k]; }
    }
    __syncthreads();
    if (wid == 0) {
        float lv[TOPK]; int li[TOPK];
        #pragma unroll
        for (int j = 0; j < TOPK; j++) {
            lv[j] = (lane < 8) ? sw_v[lane * TOPK + j] : -CUDART_INF_F;
            li[j] = (lane < 8) ? sw_i[lane * TOPK + j] : 0x7fffffff;
        }
        #pragma unroll
        for (int k = 0; k < TOPK; k++) {
            float bv = lv[0]; int bidx = li[0];
            #pragma unroll
            for (int off = 16; off; off >>= 1) {
                float ov = __shfl_down_sync(0xffffffffu, bv, off);
                int   oi = __shfl_down_sync(0xffffffffu, bidx, off);
                if (ov > bv || (ov == bv && oi < bidx)) { bv = ov; bidx = oi; }
            }
            bv   = __shfl_sync(0xffffffffu, bv, 0);
            bidx = __shfl_sync(0xffffffffu, bidx, 0);
            if (li[0] == bidx && lv[0] == bv) {
                #pragma unroll
                for (int j = 0; j < TOPK - 1; j++) { lv[j] = lv[j + 1]; li[j] = li[j + 1]; }
                lv[TOPK - 1] = -CUDART_INF_F; li[TOPK - 1] = 0x7fffffff;
            }
            if (lane == 0) {
                g_pv[(b * PARTS + part) * TOPK + k] = bv;
                g_pi[(b * PARTS + part) * TOPK + k] = bidx;
            }
        }
    }
}

// ---------------------------------------------------------------------------
// Kernel 2: merge partials (warp per row), final 64-way combine, small outputs
// ---------------------------------------------------------------------------
__global__ void __launch_bounds__(256) k_combine(const float* __restrict__ prev,
                                                 const int* __restrict__ save_id,
                                                 float* __restrict__ out) {
    const int tid = threadIdx.x, lane = tid & 31, w = tid >> 5;  // w = beam row

    __shared__ float sh_prob[NBEAM * TOPK];
    __shared__ int   sh_idx[NBEAM * TOPK];
    __shared__ int   s_bi[NBEAM], s_tbi[NBEAM];
    __shared__ float s_sel[NBEAM];

    // --- row lse from 16 partials ---
    float m = (lane < PARTS) ? g_pm[w * PARTS + lane] : -CUDART_INF_F;
    float s = (lane < PARTS) ? g_ps[w * PARTS + lane] : 0.f;
    for (int off = 16; off; off >>= 1) {
        float om = __shfl_down_sync(0xffffffffu, m, off);
        float os = __shfl_down_sync(0xffffffffu, s, off);
        if (om > m)                  { s = s * __expf(m - om) + os; m = om; }
        else if (om > -CUDART_INF_F) { s += os * __expf(om - m); }
    }
    float lse = __shfl_sync(0xffffffffu, m + logf(s), 0);

    // --- merge 128 candidates -> top-8 (warp-parallel, 4 per lane) ---
    float cv[4]; int ci[4]; bool used[4];
    #pragma unroll
    for (int j = 0; j < 4; j++) {
        int c = w * PARTS * TOPK + j * 32 + lane;
        cv[j] = g_pv[c]; ci[j] = g_pi[c]; used[j] = false;
    }
    for (int k = 0; k < TOPK; k++) {
        float bv = -CUDART_INF_F; int bidx = 0x7fffffff;
        #pragma unroll
        for (int j = 0; j < 4; j++)
            if (!used[j] && (cv[j] > bv || (cv[j] == bv && ci[j] < bidx))) { bv = cv[j]; bidx = ci[j]; }
        for (int off = 16; off; off >>= 1) {
            float ov = __shfl_down_sync(0xffffffffu, bv, off);
            int   oi = __shfl_down_sync(0xffffffffu, bidx, off);
            if (ov > bv || (ov == bv && oi < bidx)) { bv = ov; bidx = oi; }
        }
        bv   = __shfl_sync(0xffffffffu, bv, 0);
        bidx = __shfl_sync(0xffffffffu, bidx, 0);
        #pragma unroll
        for (int j = 0; j < 4; j++)
            if (cv[j] == bv && ci[j] == bidx) used[j] = true;   // token idx unique per row
        if (lane == 0) { sh_prob[w * TOPK + k] = bv - lse; sh_idx[w * TOPK + k] = bidx; }
    }
    __syncthreads();

    // --- final top-8 over 64 candidates (serial, 64 entries) ---
    if (tid == 0) {
        float cur[NBEAM * TOPK]; bool usedf[NBEAM * TOPK];
        #pragma unroll
        for (int j = 0; j < NBEAM * TOPK; j++) { cur[j] = sh_prob[j] + prev[j >> 3]; usedf[j] = false; }
        for (int k = 0; k < NBEAM; k++) {
            float bv = -CUDART_INF_F; int bj = 0;
            for (int j = 0; j < NBEAM * TOPK; j++)
                if (!usedf[j] && cur[j] > bv) { bv = cur[j]; bj = j; }
            usedf[bj] = true;
            s_bi[k]  = bj >> 3;
            s_tbi[k] = sh_idx[bj];
            s_sel[k] = bv;
            g_bi[k]  = bj >> 3;
        }
    }
    __syncthreads();

    float* o = out + KV_TOTAL;
    for (int t = tid; t < NBEAM * (HIST + 1); t += blockDim.x) {
        int ob = t / (HIST + 1), h = t % (HIST + 1);
        int v  = (h < HIST) ? save_id[s_bi[ob] * HIST + h] : s_tbi[ob];
        o[t]   = (float)v;
    }
    if (tid < NBEAM) {
        o[NBEAM * (HIST + 1) + tid]         = s_sel[tid];          // top_beam_prob
        o[NBEAM * (HIST + 1) + NBEAM + tid] = (float)s_tbi[tid];   // tbi
    }
    if (tid == 0)
        o[NBEAM * (HIST + 1) + 2 * NBEAM] = (float)s_tbi[0];       // max_logits_idx
}

// ---------------------------------------------------------------------------
// Kernel 3: KV gather — 1 GiB stream (at HBM roofline, unchanged)
// ---------------------------------------------------------------------------
__global__ void __launch_bounds__(256) k_gather(const float4* __restrict__ kv,
                                                float4* __restrict__ out) {
    const long long t = (long long)blockIdx.x * blockDim.x + threadIdx.x;
    const int l = (int)(t >> 18);
    const int r = (int)(t & (REST4 - 1));
    const long long base = (((long long)l * NBEAM) << 18) + r;

    int bi[NBEAM];
    #pragma unroll
    for (int ob = 0; ob < NBEAM; ob++) bi[ob] = g_bi[ob];

    float4 v[NBEAM];
    #pragma unroll
    for (int ob = 0; ob < NBEAM; ob++)
        v[ob] = __ldg(&kv[base + ((long long)bi[ob] << 18)]);
    #pragma unroll
    for (int ob = 0; ob < NBEAM; ob++)
        out[base + ((long long)ob << 18)] = v[ob];
}

// ---------------------------------------------------------------------------
extern "C" void kernel_launch(void* const* d_in, const int* in_sizes, int n_in,
                              void* d_out, int out_size) {
    const float* kv      = (const float*)d_in[0];
    const float* logits  = (const float*)d_in[1];
    const int*   save_id = (const int*)d_in[2];
    const float* prev    = (const float*)d_in[3];
    float*       out     = (float*)d_out;

    dim3 gA(PARTS, NBEAM);
    k_rowtop_part<<<gA, TPB_A>>>(logits);
    k_combine<<<1, 256>>>(prev, save_id, out);
    k_gather<<<32768, 256>>>((const float4*)kv, (float4*)out);
}

// round 6
// speedup vs baseline: 1.0986x; 1.0986x over previous
#include <cuda_runtime.h>
#include <math_constants.h>

#define VOCAB   50257
#define NBEAM   8
#define TOPK    8
#define HIST    128
#define PARTS   16
#define CHUNK   3142            /* ceil(50257/16) */
#define TPB_A   512
#define NV      7               /* ceil(CHUNK/TPB_A) */
#define REST4   262144          /* KV2*HEADS*SEQ*HDIM/4 */
#define KV_TOTAL 268435456LL    /* L*BEAM*KV2*HEADS*SEQ*HDIM */

__device__ float g_pm[NBEAM * PARTS];          // partial lse max
__device__ float g_ps[NBEAM * PARTS];          // partial sum exp(x - m)
__device__ float g_pv[NBEAM * PARTS * TOPK];   // per-part top-8 values
__device__ int   g_pi[NBEAM * PARTS * TOPK];   // per-part top-8 global indices
__device__ int   g_bi[NBEAM];
__device__ int   g_cnt;                        // zero-init; self-resets each run

// ---------------------------------------------------------------------------
// Fused kernel: per (part,row) partial lse + top-8; last block combines.
// ---------------------------------------------------------------------------
__global__ void __launch_bounds__(TPB_A)
k_rowtop_fused(const float* __restrict__ logits,
               const float* __restrict__ prev,
               const int* __restrict__ save_id,
               float* __restrict__ out) {
    const int part = blockIdx.x, b = blockIdx.y;
    const int tid = threadIdx.x, lane = tid & 31, wid = tid >> 5;
    const int base = part * CHUNK;
    const float* __restrict__ row = logits + (long long)b * VOCAB;

    // ---- phase 1: batched predicated loads (branch-free, MLP=NV) ----
    float val[NV]; int idx[NV];
    #pragma unroll
    for (int j = 0; j < NV; j++) {
        const int i = tid + j * TPB_A;
        const int g = base + i;
        const bool ok = (i < CHUNK) & (g < VOCAB);
        val[j] = ok ? __ldg(row + g) : -CUDART_INF_F;
        idx[j] = ok ? g : 0x7fffffff;
    }

    // ---- phase 2: branch-free two-pass lse over registers ----
    float m = val[0];
    #pragma unroll
    for (int j = 1; j < NV; j++) m = fmaxf(m, val[j]);
    float s = 0.f;
    #pragma unroll
    for (int j = 0; j < NV; j++) s += __expf(val[j] - m);   // exp(-inf)=0 pads

    // warp lse merge
    #pragma unroll
    for (int off = 16; off; off >>= 1) {
        float om = __shfl_down_sync(0xffffffffu, m, off);
        float os = __shfl_down_sync(0xffffffffu, s, off);
        if (om > m)                  { s = s * __expf(m - om) + os; m = om; }
        else if (om > -CUDART_INF_F) { s += os * __expf(om - m); }
    }
    __shared__ float swm[16], sws[16];
    if (lane == 0) { swm[wid] = m; sws[wid] = s; }

    // ---- phase 3: per-thread top-8 from registers (ascending idx = stable) ----
    float v[TOPK]; int x[TOPK];
    #pragma unroll
    for (int j = 0; j < TOPK; j++) { v[j] = -CUDART_INF_F; x[j] = 0x7fffffff; }
    #pragma unroll
    for (int j = 0; j < NV; j++) {
        if (val[j] > v[TOPK - 1]) {
            v[TOPK - 1] = val[j]; x[TOPK - 1] = idx[j];
            #pragma unroll
            for (int q = TOPK - 1; q > 0; q--) {
                if (v[q] > v[q - 1]) {
                    float tv = v[q]; v[q] = v[q - 1]; v[q - 1] = tv;
                    int   ti = x[q]; x[q] = x[q - 1]; x[q - 1] = ti;
                }
            }
        }
    }

    __syncthreads();   // swm/sws ready
    if (wid == 0) {
        float mm = (lane < 16) ? swm[lane] : -CUDART_INF_F;
        float ss = (lane < 16) ? sws[lane] : 0.f;
        #pragma unroll
        for (int off = 8; off; off >>= 1) {
            float om = __shfl_down_sync(0xffffffffu, mm, off);
            float os = __shfl_down_sync(0xffffffffu, ss, off);
            if (om > mm)                  { ss = ss * __expf(mm - om) + os; mm = om; }
            else if (om > -CUDART_INF_F)  { ss += os * __expf(om - mm); }
        }
        if (lane == 0) { g_pm[b * PARTS + part] = mm; g_ps[b * PARTS + part] = ss; }
    }

    // ---- phase 4: warp top-8 pop-merge (all registers) ----
    float rv[TOPK]; int ri[TOPK];
    #pragma unroll
    for (int k = 0; k < TOPK; k++) {
        float bv = v[0]; int bidx = x[0];
        #pragma unroll
        for (int off = 16; off; off >>= 1) {
            float ov = __shfl_down_sync(0xffffffffu, bv, off);
            int   oi = __shfl_down_sync(0xffffffffu, bidx, off);
            if (ov > bv || (ov == bv && oi < bidx)) { bv = ov; bidx = oi; }
        }
        bv   = __shfl_sync(0xffffffffu, bv, 0);
        bidx = __shfl_sync(0xffffffffu, bidx, 0);
        if (x[0] == bidx && v[0] == bv) {
            #pragma unroll
            for (int q = 0; q < TOPK - 1; q++) { v[q] = v[q + 1]; x[q] = x[q + 1]; }
            v[TOPK - 1] = -CUDART_INF_F; x[TOPK - 1] = 0x7fffffff;
        }
        rv[k] = bv; ri[k] = bidx;
    }

    // ---- phase 5: block merge of 16 warp lists via warp 0 ----
    __shared__ float sw_v[16 * TOPK];
    __shared__ int   sw_i[16 * TOPK];
    if (lane == 0) {
        #pragma unroll
        for (int k = 0; k < TOPK; k++) { sw_v[wid * TOPK + k] = rv[k]; sw_i[wid * TOPK + k] = ri[k]; }
    }
    __syncthreads();
    if (wid == 0) {
        float lv[TOPK]; int li[TOPK];
        #pragma unroll
        for (int j = 0; j < TOPK; j++) {
            lv[j] = (lane < 16) ? sw_v[lane * TOPK + j] : -CUDART_INF_F;
            li[j] = (lane < 16) ? sw_i[lane * TOPK + j] : 0x7fffffff;
        }
        #pragma unroll
        for (int k = 0; k < TOPK; k++) {
            float bv = lv[0]; int bidx = li[0];
            #pragma unroll
            for (int off = 16; off; off >>= 1) {
                float ov = __shfl_down_sync(0xffffffffu, bv, off);
                int   oi = __shfl_down_sync(0xffffffffu, bidx, off);
                if (ov > bv || (ov == bv && oi < bidx)) { bv = ov; bidx = oi; }
            }
            bv   = __shfl_sync(0xffffffffu, bv, 0);
            bidx = __shfl_sync(0xffffffffu, bidx, 0);
            if (li[0] == bidx && lv[0] == bv) {
                #pragma unroll
                for (int q = 0; q < TOPK - 1; q++) { lv[q] = lv[q + 1]; li[q] = li[q + 1]; }
                lv[TOPK - 1] = -CUDART_INF_F; li[TOPK - 1] = 0x7fffffff;
            }
            if (lane == 0) {
                g_pv[(b * PARTS + part) * TOPK + k] = bv;
                g_pi[(b * PARTS + part) * TOPK + k] = bidx;
            }
        }
    }

    // ---- phase 6: last block performs the combine ----
    __shared__ int s_last;
    if (tid == 0) {
        __threadfence();
        int c = atomicAdd(&g_cnt, 1);
        s_last = (c == PARTS * NBEAM - 1);
        if (s_last) g_cnt = 0;              // reset for next graph replay
    }
    __syncthreads();
    if (!s_last) return;                    // uniform per block

    __shared__ float sh_prob[NBEAM * TOPK];
    __shared__ int   sh_idx[NBEAM * TOPK];
    __shared__ int   s_bi[NBEAM], s_tbi[NBEAM];
    __shared__ float s_sel[NBEAM];

    const int w = wid;                      // warps 0..7 = beam rows
    if (w < NBEAM) {
        // row lse from 16 partials
        float mm = (lane < PARTS) ? g_pm[w * PARTS + lane] : -CUDART_INF_F;
        float ss = (lane < PARTS) ? g_ps[w * PARTS + lane] : 0.f;
        #pragma unroll
        for (int off = 16; off; off >>= 1) {
            float om = __shfl_down_sync(0xffffffffu, mm, off);
            float os = __shfl_down_sync(0xffffffffu, ss, off);
            if (om > mm)                  { ss = ss * __expf(mm - om) + os; mm = om; }
            else if (om > -CUDART_INF_F)  { ss += os * __expf(om - mm); }
        }
        float lse = __shfl_sync(0xffffffffu, mm + logf(ss), 0);

        // merge 128 candidates -> top-8 (4 per lane)
        float cv[4]; int ci[4]; bool used[4];
        #pragma unroll
        for (int j = 0; j < 4; j++) {
            int c = w * PARTS * TOPK + j * 32 + lane;
            cv[j] = g_pv[c]; ci[j] = g_pi[c]; used[j] = false;
        }
        for (int k = 0; k < TOPK; k++) {
            float bv = -CUDART_INF_F; int bidx = 0x7fffffff;
            #pragma unroll
            for (int j = 0; j < 4; j++)
                if (!used[j] && (cv[j] > bv || (cv[j] == bv && ci[j] < bidx))) { bv = cv[j]; bidx = ci[j]; }
            #pragma unroll
            for (int off = 16; off; off >>= 1) {
                float ov = __shfl_down_sync(0xffffffffu, bv, off);
                int   oi = __shfl_down_sync(0xffffffffu, bidx, off);
                if (ov > bv || (ov == bv && oi < bidx)) { bv = ov; bidx = oi; }
            }
            bv   = __shfl_sync(0xffffffffu, bv, 0);
            bidx = __shfl_sync(0xffffffffu, bidx, 0);
            #pragma unroll
            for (int j = 0; j < 4; j++)
                if (cv[j] == bv && ci[j] == bidx) used[j] = true;
            if (lane == 0) { sh_prob[w * TOPK + k] = bv - lse; sh_idx[w * TOPK + k] = bidx; }
        }
    }
    __syncthreads();

    if (tid == 0) {
        float cur[NBEAM * TOPK]; bool usedf[NBEAM * TOPK];
        #pragma unroll
        for (int j = 0; j < NBEAM * TOPK; j++) { cur[j] = sh_prob[j] + prev[j >> 3]; usedf[j] = false; }
        for (int k = 0; k < NBEAM; k++) {
            float bv = -CUDART_INF_F; int bj = 0;
            for (int j = 0; j < NBEAM * TOPK; j++)
                if (!usedf[j] && cur[j] > bv) { bv = cur[j]; bj = j; }
            usedf[bj] = true;
            s_bi[k]  = bj >> 3;
            s_tbi[k] = sh_idx[bj];
            s_sel[k] = bv;
            g_bi[k]  = bj >> 3;
        }
    }
    __syncthreads();

    float* o = out + KV_TOTAL;
    for (int t = tid; t < NBEAM * (HIST + 1); t += TPB_A) {
        int ob = t / (HIST + 1), h = t % (HIST + 1);
        int vv = (h < HIST) ? save_id[s_bi[ob] * HIST + h] : s_tbi[ob];
        o[t]   = (float)vv;
    }
    if (tid < NBEAM) {
        o[NBEAM * (HIST + 1) + tid]         = s_sel[tid];          // top_beam_prob
        o[NBEAM * (HIST + 1) + NBEAM + tid] = (float)s_tbi[tid];   // tbi
    }
    if (tid == 0)
        o[NBEAM * (HIST + 1) + 2 * NBEAM] = (float)s_tbi[0];       // max_logits_idx
}

// ---------------------------------------------------------------------------
// KV gather — 1 GiB stream (at HBM roofline, unchanged)
// ---------------------------------------------------------------------------
__global__ void __launch_bounds__(256) k_gather(const float4* __restrict__ kv,
                                                float4* __restrict__ out) {
    const long long t = (long long)blockIdx.x * blockDim.x + threadIdx.x;
    const int l = (int)(t >> 18);
    const int r = (int)(t & (REST4 - 1));
    const long long base = (((long long)l * NBEAM) << 18) + r;

    int bi[NBEAM];
    #pragma unroll
    for (int ob = 0; ob < NBEAM; ob++) bi[ob] = g_bi[ob];

    float4 v[NBEAM];
    #pragma unroll
    for (int ob = 0; ob < NBEAM; ob++)
        v[ob] = __ldg(&kv[base + ((long long)bi[ob] << 18)]);
    #pragma unroll
    for (int ob = 0; ob < NBEAM; ob++)
        out[base + ((long long)ob << 18)] = v[ob];
}

// ---------------------------------------------------------------------------
extern "C" void kernel_launch(void* const* d_in, const int* in_sizes, int n_in,
                              void* d_out, int out_size) {
    const float* kv      = (const float*)d_in[0];
    const float* logits  = (const float*)d_in[1];
    const int*   save_id = (const int*)d_in[2];
    const float* prev    = (const float*)d_in[3];
    float*       out     = (float*)d_out;

    dim3 gA(PARTS, NBEAM);
    k_rowtop_fused<<<gA, TPB_A>>>(logits, prev, save_id, out);
    k_gather<<<32768, 256>>>((const float4*)kv, (float4*)out);
}

// round 7
// speedup vs baseline: 1.1041x; 1.0050x over previous
#include <cuda_runtime.h>
#include <math_constants.h>

#define VOCAB   50257
#define NBEAM   8
#define TOPK    8
#define HIST    128
#define PARTS   16
#define CHUNK   3142            /* ceil(50257/16) */
#define TPB     256
#define NV      13              /* ceil(CHUNK/TPB) */
#define ROWBLK  (PARTS*NBEAM)   /* 128 */
#define GRID    32768
#define REST4   262144          /* KV2*HEADS*SEQ*HDIM/4 */
#define KV_TOTAL 268435456LL

__device__ float g_pm[NBEAM * PARTS];
__device__ float g_ps[NBEAM * PARTS];
__device__ float g_pv[NBEAM * PARTS * TOPK];
__device__ int   g_pi[NBEAM * PARTS * TOPK];
__device__ int   g_bi[NBEAM];
__device__ int   g_cnt;     // rowtop blocks done   (self-resets)
__device__ int   g_cnt2;    // all blocks done      (self-resets)
__device__ int   g_flag;    // indices-ready        (self-resets)

__global__ void __launch_bounds__(TPB)
k_fused(const float* __restrict__ logits,
        const float* __restrict__ prev,
        const int*   __restrict__ save_id,
        const float4* __restrict__ kv,
        float4* __restrict__ out) {
    const int bid = blockIdx.x;
    const int tid = threadIdx.x, lane = tid & 31, wid = tid >> 5;

    // =====================================================================
    // Role A: blocks 0..127 compute per-(part,row) lse + top-8 partials
    // =====================================================================
    if (bid < ROWBLK) {
        const int part = bid & (PARTS - 1), b = bid >> 4;
        const int base = part * CHUNK;
        const float* __restrict__ row = logits + (long long)b * VOCAB;

        // ---- batched predicated loads (branch-free, MLP=NV) ----
        float val[NV]; int idx[NV];
        #pragma unroll
        for (int j = 0; j < NV; j++) {
            const int i = tid + j * TPB;
            const int g = base + i;
            const bool ok = (i < CHUNK) & (g < VOCAB);
            val[j] = ok ? __ldg(row + g) : -CUDART_INF_F;
            idx[j] = ok ? g : 0x7fffffff;
        }

        // ---- branch-free two-pass lse over registers ----
        float m = val[0];
        #pragma unroll
        for (int j = 1; j < NV; j++) m = fmaxf(m, val[j]);
        float s = 0.f;
        #pragma unroll
        for (int j = 0; j < NV; j++) s += __expf(val[j] - m);

        #pragma unroll
        for (int off = 16; off; off >>= 1) {
            float om = __shfl_down_sync(0xffffffffu, m, off);
            float os = __shfl_down_sync(0xffffffffu, s, off);
            if (om > m)                  { s = s * __expf(m - om) + os; m = om; }
            else if (om > -CUDART_INF_F) { s += os * __expf(om - m); }
        }
        __shared__ float swm[8], sws[8];
        if (lane == 0) { swm[wid] = m; sws[wid] = s; }

        // ---- per-thread top-8 from registers (ascending idx = stable) ----
        float v[TOPK]; int x[TOPK];
        #pragma unroll
        for (int j = 0; j < TOPK; j++) { v[j] = -CUDART_INF_F; x[j] = 0x7fffffff; }
        #pragma unroll
        for (int j = 0; j < NV; j++) {
            if (val[j] > v[TOPK - 1]) {
                v[TOPK - 1] = val[j]; x[TOPK - 1] = idx[j];
                #pragma unroll
                for (int q = TOPK - 1; q > 0; q--) {
                    if (v[q] > v[q - 1]) {
                        float tv = v[q]; v[q] = v[q - 1]; v[q - 1] = tv;
                        int   ti = x[q]; x[q] = x[q - 1]; x[q - 1] = ti;
                    }
                }
            }
        }

        __syncthreads();
        if (wid == 0) {
            float mm = (lane < 8) ? swm[lane] : -CUDART_INF_F;
            float ss = (lane < 8) ? sws[lane] : 0.f;
            #pragma unroll
            for (int off = 4; off; off >>= 1) {
                float om = __shfl_down_sync(0xffffffffu, mm, off);
                float os = __shfl_down_sync(0xffffffffu, ss, off);
                if (om > mm)                  { ss = ss * __expf(mm - om) + os; mm = om; }
                else if (om > -CUDART_INF_F)  { ss += os * __expf(om - mm); }
            }
            if (lane == 0) { g_pm[b * PARTS + part] = mm; g_ps[b * PARTS + part] = ss; }
        }

        // ---- warp top-8 pop-merge ----
        float rv[TOPK]; int ri[TOPK];
        #pragma unroll
        for (int k = 0; k < TOPK; k++) {
            float bv = v[0]; int bidx = x[0];
            #pragma unroll
            for (int off = 16; off; off >>= 1) {
                float ov = __shfl_down_sync(0xffffffffu, bv, off);
                int   oi = __shfl_down_sync(0xffffffffu, bidx, off);
                if (ov > bv || (ov == bv && oi < bidx)) { bv = ov; bidx = oi; }
            }
            bv   = __shfl_sync(0xffffffffu, bv, 0);
            bidx = __shfl_sync(0xffffffffu, bidx, 0);
            if (x[0] == bidx && v[0] == bv) {
                #pragma unroll
                for (int q = 0; q < TOPK - 1; q++) { v[q] = v[q + 1]; x[q] = x[q + 1]; }
                v[TOPK - 1] = -CUDART_INF_F; x[TOPK - 1] = 0x7fffffff;
            }
            rv[k] = bv; ri[k] = bidx;
        }

        // ---- block merge of 8 warp lists ----
        __shared__ float sw_v[8 * TOPK];
        __shared__ int   sw_i[8 * TOPK];
        if (lane == 0) {
            #pragma unroll
            for (int k = 0; k < TOPK; k++) { sw_v[wid * TOPK + k] = rv[k]; sw_i[wid * TOPK + k] = ri[k]; }
        }
        __syncthreads();
        if (wid == 0) {
            float lv[TOPK]; int li[TOPK];
            #pragma unroll
            for (int j = 0; j < TOPK; j++) {
                lv[j] = (lane < 8) ? sw_v[lane * TOPK + j] : -CUDART_INF_F;
                li[j] = (lane < 8) ? sw_i[lane * TOPK + j] : 0x7fffffff;
            }
            #pragma unroll
            for (int k = 0; k < TOPK; k++) {
                float bv = lv[0]; int bidx = li[0];
                #pragma unroll
                for (int off = 16; off; off >>= 1) {
                    float ov = __shfl_down_sync(0xffffffffu, bv, off);
                    int   oi = __shfl_down_sync(0xffffffffu, bidx, off);
                    if (ov > bv || (ov == bv && oi < bidx)) { bv = ov; bidx = oi; }
                }
                bv   = __shfl_sync(0xffffffffu, bv, 0);
                bidx = __shfl_sync(0xffffffffu, bidx, 0);
                if (li[0] == bidx && lv[0] == bv) {
                    #pragma unroll
                    for (int q = 0; q < TOPK - 1; q++) { lv[q] = lv[q + 1]; li[q] = li[q + 1]; }
                    lv[TOPK - 1] = -CUDART_INF_F; li[TOPK - 1] = 0x7fffffff;
                }
                if (lane == 0) {
                    g_pv[(b * PARTS + part) * TOPK + k] = bv;
                    g_pi[(b * PARTS + part) * TOPK + k] = bidx;
                }
            }
        }

        // ---- last rowtop block: combine + raise flag ----
        __shared__ int s_last;
        if (tid == 0) {
            __threadfence();
            int c = atomicAdd(&g_cnt, 1);
            s_last = (c == ROWBLK - 1);
            if (s_last) g_cnt = 0;
        }
        __syncthreads();
        if (s_last) {
            __shared__ float sh_prob[NBEAM * TOPK];
            __shared__ int   sh_idx[NBEAM * TOPK];
            __shared__ int   s_bi[NBEAM], s_tbi[NBEAM];
            __shared__ float s_sel[NBEAM];

            const int w = wid;  // 8 warps = 8 beam rows
            {
                float mm = (lane < PARTS) ? g_pm[w * PARTS + lane] : -CUDART_INF_F;
                float ss = (lane < PARTS) ? g_ps[w * PARTS + lane] : 0.f;
                #pragma unroll
                for (int off = 16; off; off >>= 1) {
                    float om = __shfl_down_sync(0xffffffffu, mm, off);
                    float os = __shfl_down_sync(0xffffffffu, ss, off);
                    if (om > mm)                  { ss = ss * __expf(mm - om) + os; mm = om; }
                    else if (om > -CUDART_INF_F)  { ss += os * __expf(om - mm); }
                }
                float lse = __shfl_sync(0xffffffffu, mm + logf(ss), 0);

                float cv[4]; int ci[4]; bool used[4];
                #pragma unroll
                for (int j = 0; j < 4; j++) {
                    int c2 = w * PARTS * TOPK + j * 32 + lane;
                    cv[j] = g_pv[c2]; ci[j] = g_pi[c2]; used[j] = false;
                }
                for (int k = 0; k < TOPK; k++) {
                    float bv = -CUDART_INF_F; int bidx = 0x7fffffff;
                    #pragma unroll
                    for (int j = 0; j < 4; j++)
                        if (!used[j] && (cv[j] > bv || (cv[j] == bv && ci[j] < bidx))) { bv = cv[j]; bidx = ci[j]; }
                    #pragma unroll
                    for (int off = 16; off; off >>= 1) {
                        float ov = __shfl_down_sync(0xffffffffu, bv, off);
                        int   oi = __shfl_down_sync(0xffffffffu, bidx, off);
                        if (ov > bv || (ov == bv && oi < bidx)) { bv = ov; bidx = oi; }
                    }
                    bv   = __shfl_sync(0xffffffffu, bv, 0);
                    bidx = __shfl_sync(0xffffffffu, bidx, 0);
                    #pragma unroll
                    for (int j = 0; j < 4; j++)
                        if (cv[j] == bv && ci[j] == bidx) used[j] = true;
                    if (lane == 0) { sh_prob[w * TOPK + k] = bv - lse; sh_idx[w * TOPK + k] = bidx; }
                }
            }
            __syncthreads();

            // final 64-candidate top-8, warp 0, 2 cands/lane (val desc, flat idx asc)
            if (wid == 0) {
                const int j0 = lane * 2, j1 = lane * 2 + 1;
                float c0 = sh_prob[j0] + __ldg(prev + (j0 >> 3));
                float c1 = sh_prob[j1] + __ldg(prev + (j1 >> 3));
                bool u0 = false, u1 = false;
                for (int k = 0; k < NBEAM; k++) {
                    float bv = -CUDART_INF_F; int bj = 0x7fffffff;
                    if (!u0)                                   { bv = c0; bj = j0; }
                    if (!u1 && (c1 > bv || (c1 == bv && j1 < bj))) { bv = c1; bj = j1; }
                    #pragma unroll
                    for (int off = 16; off; off >>= 1) {
                        float ov = __shfl_down_sync(0xffffffffu, bv, off);
                        int   oj = __shfl_down_sync(0xffffffffu, bj, off);
                        if (ov > bv || (ov == bv && oj < bj)) { bv = ov; bj = oj; }
                    }
                    bv = __shfl_sync(0xffffffffu, bv, 0);
                    bj = __shfl_sync(0xffffffffu, bj, 0);
                    if (bj == j0) u0 = true;
                    if (bj == j1) u1 = true;
                    if (lane == 0) {
                        s_bi[k]  = bj >> 3;
                        s_tbi[k] = sh_idx[bj];
                        s_sel[k] = bv;
                        g_bi[k]  = bj >> 3;
                    }
                }
            }
            __syncthreads();

            float* o = (float*)out + KV_TOTAL;
            for (int t = tid; t < NBEAM * (HIST + 1); t += TPB) {
                int ob = t / (HIST + 1), h = t % (HIST + 1);
                int vv = (h < HIST) ? save_id[s_bi[ob] * HIST + h] : s_tbi[ob];
                o[t]   = (float)vv;
            }
            if (tid < NBEAM) {
                o[NBEAM * (HIST + 1) + tid]         = s_sel[tid];
                o[NBEAM * (HIST + 1) + NBEAM + tid] = (float)s_tbi[tid];
            }
            if (tid == 0) {
                o[NBEAM * (HIST + 1) + 2 * NBEAM] = (float)s_tbi[0];
                __threadfence();
                *((volatile int*)&g_flag) = 1;     // release: g_bi visible
            }
        }
    }

    // =====================================================================
    // Role B (all blocks): wait for indices, then gather this block's tile
    // =====================================================================
    __shared__ int sh_gbi[NBEAM];
    if (tid == 0) {
        while (*((volatile int*)&g_flag) == 0) { }
        __threadfence();                          // acquire
        #pragma unroll
        for (int ob = 0; ob < NBEAM; ob++)
            sh_gbi[ob] = *((volatile int*)&g_bi[ob]);
    }
    __syncthreads();

    {
        const long long t = (long long)bid * TPB + tid;   // [0, 32*REST4)
        const int l = (int)(t >> 18);
        const int r = (int)(t & (REST4 - 1));
        const long long base = (((long long)l * NBEAM) << 18) + r;

        int bi[NBEAM];
        #pragma unroll
        for (int ob = 0; ob < NBEAM; ob++) bi[ob] = sh_gbi[ob];

        float4 v[NBEAM];
        #pragma unroll
        for (int ob = 0; ob < NBEAM; ob++)
            v[ob] = __ldcs(&kv[base + ((long long)bi[ob] << 18)]);
        #pragma unroll
        for (int ob = 0; ob < NBEAM; ob++)
            __stcs(&out[base + ((long long)ob << 18)], v[ob]);
    }

    // ---- grid-done counter resets flag for next graph replay ----
    if (tid == 0) {
        int c = atomicAdd(&g_cnt2, 1);
        if (c == GRID - 1) { g_flag = 0; g_cnt2 = 0; }
    }
}

// ---------------------------------------------------------------------------
extern "C" void kernel_launch(void* const* d_in, const int* in_sizes, int n_in,
                              void* d_out, int out_size) {
    const float* kv      = (const float*)d_in[0];
    const float* logits  = (const float*)d_in[1];
    const int*   save_id = (const int*)d_in[2];
    const float* prev    = (const float*)d_in[3];

    k_fused<<<GRID, TPB>>>(logits, prev, save_id,
                           (const float4*)kv, (float4*)d_out);
}